// round 1
// baseline (speedup 1.0000x reference)
#include <cuda_runtime.h>

// Problem constants
#define BATCH 32
#define IMG_H 480
#define IMG_W 640
#define OUT_H 470
#define OUT_W 630
#define WS    11

// Tiling
#define TILE_W 64
#define TILE_H 32
#define IN_W   (TILE_W + WS - 1)   // 74
#define IN_W_PAD 76                // pad to multiple of 4
#define IN_H   (TILE_H + WS - 1)   // 42
#define MID_W  TILE_W              // 64

#define GX 10   // ceil(630/64)
#define GY 15   // ceil(470/32)
#define NBLOCKS (GX * GY * BATCH)  // 4800
#define NTHREADS 256

// Normalized 1D Gaussian, sigma=1.5, ws=11 (symmetric)
__device__ __constant__ const float W11_dummy = 0.f; // keep nvcc happy if unused
static __device__ __forceinline__ float gw(int t) {
    constexpr float w[11] = {
        0.00102839f, 0.00759866f, 0.03600077f, 0.10936124f, 0.21300553f,
        0.26601172f,
        0.21300553f, 0.10936124f, 0.03600077f, 0.00759866f, 0.00102839f
    };
    return w[t];
}

__device__ float g_partials[NBLOCKS];

__global__ __launch_bounds__(NTHREADS, 2)
void ssim_tile_kernel(const float* __restrict__ img1,
                      const float* __restrict__ img2)
{
    extern __shared__ float smem[];
    float* s_x   = smem;                         // IN_H * IN_W_PAD
    float* s_y   = s_x + IN_H * IN_W_PAD;        // IN_H * IN_W_PAD
    float* s_mid = s_y + IN_H * IN_W_PAD;        // 5 * IN_H * MID_W

    const int tid = threadIdx.x;
    const int bz  = blockIdx.z;                  // batch
    const int r0  = blockIdx.y * TILE_H;         // output row origin
    const int c0  = blockIdx.x * TILE_W;         // output col origin

    const float* im1 = img1 + (size_t)bz * IMG_H * IMG_W;
    const float* im2 = img2 + (size_t)bz * IMG_H * IMG_W;

    // ---- Stage 1: load input tile (with halo), OOB -> 0 ----
    for (int i = tid; i < IN_H * IN_W; i += NTHREADS) {
        int r = i / IN_W;
        int c = i - r * IN_W;
        int gr = r0 + r;
        int gc = c0 + c;
        float v1 = 0.f, v2 = 0.f;
        if (gr < IMG_H && gc < IMG_W) {
            int idx = gr * IMG_W + gc;
            v1 = im1[idx];
            v2 = im2[idx];
        }
        s_x[r * IN_W_PAD + c] = v1;
        s_y[r * IN_W_PAD + c] = v2;
    }
    __syncthreads();

    // ---- Stage 2: horizontal conv, 5 channels, 4-wide strips ----
    // products (x^2, y^2, xy) computed on the fly: 2 LDS floats per tap.
    for (int s = tid; s < IN_H * (TILE_W / 4); s += NTHREADS) {
        int row = s >> 4;            // s / 16
        int cq  = (s & 15) << 2;     // (s % 16) * 4
        const float* px = s_x + row * IN_W_PAD + cq;
        const float* py = s_y + row * IN_W_PAD + cq;

        float a0[4] = {0.f, 0.f, 0.f, 0.f};  // mu1
        float a1[4] = {0.f, 0.f, 0.f, 0.f};  // mu2
        float a2[4] = {0.f, 0.f, 0.f, 0.f};  // xx
        float a3[4] = {0.f, 0.f, 0.f, 0.f};  // yy
        float a4[4] = {0.f, 0.f, 0.f, 0.f};  // xy

        #pragma unroll
        for (int k = 0; k < WS + 3; k++) {   // 14 taps serve 4 outputs
            float xv = px[k];
            float yv = py[k];
            float xx = xv * xv;
            float yy = yv * yv;
            float xy = xv * yv;
            #pragma unroll
            for (int o = 0; o < 4; o++) {
                int t = k - o;
                if (t >= 0 && t < WS) {
                    float w = gw(t);         // compile-time const -> FFMA-imm
                    a0[o] += w * xv;
                    a1[o] += w * yv;
                    a2[o] += w * xx;
                    a3[o] += w * yy;
                    a4[o] += w * xy;
                }
            }
        }
        float* m = s_mid + row * MID_W + cq;
        #pragma unroll
        for (int o = 0; o < 4; o++) {
            m[0 * IN_H * MID_W + o] = a0[o];
            m[1 * IN_H * MID_W + o] = a1[o];
            m[2 * IN_H * MID_W + o] = a2[o];
            m[3 * IN_H * MID_W + o] = a3[o];
            m[4 * IN_H * MID_W + o] = a4[o];
        }
    }
    __syncthreads();

    // ---- Stage 3: vertical conv + SSIM + local sum, 4-tall strips ----
    const float C1 = 1.0f;   // (0.01*100)^2
    const float C2 = 9.0f;   // (0.03*100)^2
    float lsum = 0.f;

    for (int s = tid; s < (TILE_H / 4) * TILE_W; s += NTHREADS) {
        int rq = (s / TILE_W) * 4;
        int c  = s - (s / TILE_W) * TILE_W;

        float m1[4]  = {0.f, 0.f, 0.f, 0.f};
        float m2[4]  = {0.f, 0.f, 0.f, 0.f};
        float exx[4] = {0.f, 0.f, 0.f, 0.f};
        float eyy[4] = {0.f, 0.f, 0.f, 0.f};
        float exy[4] = {0.f, 0.f, 0.f, 0.f};

        #pragma unroll
        for (int k = 0; k < WS + 3; k++) {
            int row = rq + k;
            const float* m = s_mid + row * MID_W + c;
            float v0 = m[0 * IN_H * MID_W];
            float v1 = m[1 * IN_H * MID_W];
            float v2 = m[2 * IN_H * MID_W];
            float v3 = m[3 * IN_H * MID_W];
            float v4 = m[4 * IN_H * MID_W];
            #pragma unroll
            for (int o = 0; o < 4; o++) {
                int t = k - o;
                if (t >= 0 && t < WS) {
                    float w = gw(t);
                    m1[o]  += w * v0;
                    m2[o]  += w * v1;
                    exx[o] += w * v2;
                    eyy[o] += w * v3;
                    exy[o] += w * v4;
                }
            }
        }

        int gc = c0 + c;
        if (gc < OUT_W) {
            #pragma unroll
            for (int o = 0; o < 4; o++) {
                int gr = r0 + rq + o;
                if (gr < OUT_H) {
                    float mu1 = m1[o], mu2 = m2[o];
                    float mu1sq = mu1 * mu1;
                    float mu2sq = mu2 * mu2;
                    float mu12  = mu1 * mu2;
                    float s1  = exx[o] - mu1sq;
                    float s2  = eyy[o] - mu2sq;
                    float s12 = exy[o] - mu12;
                    float v1 = 2.f * s12 + C2;
                    float v2 = s1 + s2 + C2;
                    float num = (2.f * mu12 + C1) * v1;
                    float den = (mu1sq + mu2sq + C1) * v2;
                    lsum += __fdividef(num, den);
                }
            }
        }
    }

    // ---- Stage 4: block reduction (deterministic), write partial ----
    #pragma unroll
    for (int off = 16; off > 0; off >>= 1)
        lsum += __shfl_down_sync(0xffffffffu, lsum, off);

    int warp = tid >> 5;
    int lane = tid & 31;
    // s_x region is dead after stage 2's __syncthreads barrier (stage 3 only
    // reads s_mid), safe to reuse as reduction scratch.
    if (lane == 0) s_x[warp] = lsum;
    __syncthreads();
    if (tid == 0) {
        float t = 0.f;
        #pragma unroll
        for (int i = 0; i < NTHREADS / 32; i++) t += s_x[i];
        int bidx = (blockIdx.z * GY + blockIdx.y) * GX + blockIdx.x;
        g_partials[bidx] = t;
    }
}

__global__ void ssim_finalize_kernel(float* __restrict__ out)
{
    __shared__ float sh[NTHREADS];
    int tid = threadIdx.x;
    float s = 0.f;
    for (int i = tid; i < NBLOCKS; i += NTHREADS)
        s += g_partials[i];
    sh[tid] = s;
    __syncthreads();
    #pragma unroll
    for (int off = NTHREADS / 2; off > 0; off >>= 1) {
        if (tid < off) sh[tid] += sh[tid + off];
        __syncthreads();
    }
    if (tid == 0) {
        float mean = sh[0] * (1.0f / ((float)BATCH * OUT_H * OUT_W));
        out[0] = (1.0f - mean) * 0.5f;
    }
}

extern "C" void kernel_launch(void* const* d_in, const int* in_sizes, int n_in,
                              void* d_out, int out_size)
{
    const float* img1 = (const float*)d_in[0];
    const float* img2 = (const float*)d_in[1];
    float* out = (float*)d_out;

    size_t smem_bytes = (size_t)(2 * IN_H * IN_W_PAD + 5 * IN_H * MID_W) * sizeof(float);
    cudaFuncSetAttribute(ssim_tile_kernel,
                         cudaFuncAttributeMaxDynamicSharedMemorySize,
                         (int)smem_bytes);

    dim3 grid(GX, GY, BATCH);
    ssim_tile_kernel<<<grid, NTHREADS, smem_bytes>>>(img1, img2);
    ssim_finalize_kernel<<<1, NTHREADS>>>(out);
}